// round 5
// baseline (speedup 1.0000x reference)
#include <cuda_runtime.h>

#define NPTS    16384
#define NB      1024
#define XMIN    (-5.0f)
#define XW      (10.0f / (float)NB)
#define INVW    ((float)NB / 10.0f)
#define PAD     6                         // initial bins each side of warp span
#define EXPBINS 4                         // bins added per side per expansion
#define STPB    256                       // search threads/block (8 warps)
#define SGRID   (NPTS / STPB)             // 64 search blocks per pass

typedef unsigned int u32;

// set 0 = predict, set 1 = target
__device__ u32    g_cnt[2][NB];
__device__ u32    g_cur[2][NB];
__device__ int    g_off[2][NB + 1];
__device__ float4 g_pts[2][NPTS];         // binned points (x,y,z, 0.5*|p|^2)
__device__ int    g_idx[2][NPTS];         // original index of binned point
__device__ float  g_d2[2][NPTS];          // min sq-dist per query (by orig idx)

__device__ __forceinline__ int bin_of(float x) {
    int b = (int)((x - XMIN) * INVW);
    return min(max(b, 0), NB - 1);
}

// ---------- K0: zero counters ----------
__global__ void k_zero() {
    int i = blockIdx.x * blockDim.x + threadIdx.x;
    if (i < 2 * NB) {
        ((u32*)g_cnt)[i] = 0;
        ((u32*)g_cur)[i] = 0;
    }
}

// ---------- K1: histogram ----------
__global__ void k_count(const float* __restrict__ pr, const float* __restrict__ tg) {
    int i = blockIdx.x * blockDim.x + threadIdx.x;
    if (i >= 2 * NPTS) return;
    int s = (i >= NPTS);
    int j = i - s * NPTS;
    const float* src = s ? tg : pr;
    atomicAdd(&g_cnt[s][bin_of(src[3 * j])], 1u);
}

// ---------- K2: prefix sums (one block, NB threads) ----------
__global__ void __launch_bounds__(NB) k_scan() {
    __shared__ int sh[NB];
    int tid = threadIdx.x;
#pragma unroll
    for (int s = 0; s < 2; s++) {
        sh[tid] = (int)g_cnt[s][tid];
        __syncthreads();
        for (int d = 1; d < NB; d <<= 1) {
            int v = sh[tid];
            if (tid >= d) v += sh[tid - d];
            __syncthreads();
            sh[tid] = v;
            __syncthreads();
        }
        g_off[s][tid + 1] = sh[tid];
        if (tid == 0) g_off[s][0] = 0;
        __syncthreads();
    }
}

// ---------- K3: scatter into binned order ----------
__global__ void k_scatter(const float* __restrict__ pr, const float* __restrict__ tg) {
    int i = blockIdx.x * blockDim.x + threadIdx.x;
    if (i >= 2 * NPTS) return;
    int s = (i >= NPTS);
    int j = i - s * NPTS;
    const float* src = s ? tg : pr;
    float x = src[3 * j], y = src[3 * j + 1], z = src[3 * j + 2];
    int b = bin_of(x);
    int pos = g_off[s][b] + (int)atomicAdd(&g_cur[s][b], 1u);
    g_pts[s][pos] = make_float4(x, y, z, 0.5f * (x * x + y * y + z * z));
    g_idx[s][pos] = j;
}

// ---------- warp-local eval of ref range [beg,end) ----------
// All lanes read the same ref (uniform broadcast LDG); each lane owns one query.
__device__ __forceinline__ void eval_range(const float4* __restrict__ refs,
                                           int beg, int end,
                                           float nqx, float nqy, float nqz,
                                           float& m0, float& m1) {
    int j = beg;
#pragma unroll 2
    for (; j + 2 <= end; j += 2) {
        float4 t0 = __ldg(&refs[j]);
        float4 t1 = __ldg(&refs[j + 1]);
        float e0 = __fmaf_rn(nqx, t0.x, t0.w);
        e0 = __fmaf_rn(nqy, t0.y, e0);
        e0 = __fmaf_rn(nqz, t0.z, e0);
        float e1 = __fmaf_rn(nqx, t1.x, t1.w);
        e1 = __fmaf_rn(nqy, t1.y, e1);
        e1 = __fmaf_rn(nqz, t1.z, e1);
        m0 = fminf(m0, e0);
        m1 = fminf(m1, e1);
    }
    if (j < end) {
        float4 t0 = __ldg(&refs[j]);
        float e0 = __fmaf_rn(nqx, t0.x, t0.w);
        e0 = __fmaf_rn(nqy, t0.y, e0);
        e0 = __fmaf_rn(nqz, t0.z, e0);
        m0 = fminf(m0, e0);
    }
}

// ---------- K4: warp-autonomous pruned exact NN search ----------
// blockIdx.y = pass (0: queries=predict vs refs=target; 1: reverse)
__global__ void __launch_bounds__(STPB)
k_search() {
    const int pass = blockIdx.y;
    const int qset = pass, rset = 1 - pass;
    const int lane = threadIdx.x & 31;
    const int qpos = blockIdx.x * STPB + threadIdx.x;   // 32 consecutive binned queries/warp

    const float4 q = g_pts[qset][qpos];
    const int myidx = g_idx[qset][qpos];
    const float nqx = -q.x, nqy = -q.y, nqz = -q.z;

    // binned order is sorted by bin: lane0 has warp-min bin, lane31 warp-max
    int qb = bin_of(q.x);
    int l = max(__shfl_sync(0xFFFFFFFFu, qb, 0) - PAD, 0);
    int r = min(__shfl_sync(0xFFFFFFFFu, qb, 31) + PAD, NB - 1);

    const float4* __restrict__ refs = g_pts[rset];
    const int* __restrict__ off = g_off[rset];

    const float INF = __int_as_float(0x7f800000);
    float m0 = INF, m1 = INF;

    eval_range(refs, off[l], off[r + 1], nqx, nqy, nqz, m0, m1);

    while (true) {
        float m = fminf(m0, m1);
        float myd2 = fmaxf(2.0f * (m + q.w), 0.0f);
        float bndL = XMIN + (float)l * XW;
        float bndR = XMIN + (float)(r + 1) * XW;
        float dl = q.x - bndL;             // valid lower bound when l > 0
        float dr = bndR - q.x;             // valid lower bound when r < NB-1
        bool needL = (l > 0) && (dl * dl < myd2);
        bool needR = (r < NB - 1) && (dr * dr < myd2);
        bool anyL = __any_sync(0xFFFFFFFFu, needL);
        bool anyR = __any_sync(0xFFFFFFFFu, needR);
        if (!anyL && !anyR) break;

        int nl = anyL ? max(l - EXPBINS, 0) : l;
        int nr = anyR ? min(r + EXPBINS, NB - 1) : r;
        if (anyL) eval_range(refs, off[nl], off[l], nqx, nqy, nqz, m0, m1);
        if (anyR) eval_range(refs, off[r + 1], off[nr + 1], nqx, nqy, nqz, m0, m1);
        l = nl; r = nr;
    }

    float m = fminf(m0, m1);
    g_d2[pass][myidx] = fmaxf(2.0f * (m + q.w), 0.0f);
    (void)lane;
}

// ---------- K5: deterministic fixed-order reduction ----------
__global__ void __launch_bounds__(1024)
k_reduce(float* __restrict__ out) {
    __shared__ float sh[1024];
    const float* d2 = (const float*)g_d2;   // 2*NPTS floats, fixed order
    float s = 0.0f;
    for (int i = threadIdx.x; i < 2 * NPTS; i += 1024)
        s += d2[i];
    sh[threadIdx.x] = s;
    __syncthreads();
#pragma unroll
    for (int o = 512; o > 0; o >>= 1) {
        if (threadIdx.x < o) sh[threadIdx.x] += sh[threadIdx.x + o];
        __syncthreads();
    }
    if (threadIdx.x == 0)
        out[0] = sh[0] * (1.0f / (float)NPTS);
}

extern "C" void kernel_launch(void* const* d_in, const int* in_sizes, int n_in,
                              void* d_out, int out_size) {
    const float* pr = (const float*)d_in[0];   // predict [1,16384,3]
    const float* tg = (const float*)d_in[1];   // target  [1,16384,3]
    float* out = (float*)d_out;

    k_zero<<<(2 * NB + 255) / 256, 256>>>();
    k_count<<<(2 * NPTS + 255) / 256, 256>>>(pr, tg);
    k_scan<<<1, NB>>>();
    k_scatter<<<(2 * NPTS + 255) / 256, 256>>>(pr, tg);

    dim3 grid(SGRID, 2);
    k_search<<<grid, STPB>>>();

    k_reduce<<<1, 1024>>>(out);
}

// round 6
// speedup vs baseline: 1.2327x; 1.2327x over previous
#include <cuda_runtime.h>

#define NPTS   16384
#define NB     1024
#define XMIN   (-5.0f)
#define XW     (10.0f / (float)NB)
#define INVW   ((float)NB / 10.0f)
#define CH     512                        // queries per chunk / refs per segment
#define NCHUNK (NPTS / CH)                // 32
#define KSEG   5                          // ref chunks per query chunk (c-2..c+2)
#define TPB    256                        // search threads (QPT=2)
#define PREPT  1024
#define FIXT   1024
#define EXPB   8                          // bins per fixup expansion step

typedef unsigned int u32;

// set 0 = predict, set 1 = target; pass 0: queries=set0 vs refs=set1
__device__ int    g_off[2][NB + 1];
__device__ float4 g_pts[2][NPTS];         // x-binned points (x,y,z, 0.5*|p|^2)
__device__ u32    g_minbits[2][NPTS];     // by binned query position
__device__ float  g_d2[2][NPTS];

__device__ __forceinline__ int bin_of(float x) {
    int b = (int)((x - XMIN) * INVW);
    return min(max(b, 0), NB - 1);
}
__device__ __forceinline__ u32 fflip(float f) {
    u32 u = __float_as_uint(f);
    return (u & 0x80000000u) ? ~u : (u | 0x80000000u);
}
__device__ __forceinline__ float funflip(u32 u) {
    u = (u & 0x80000000u) ? (u ^ 0x80000000u) : ~u;
    return __uint_as_float(u);
}

// ---------- K1: fused prep (one block per set) ----------
__global__ void __launch_bounds__(PREPT)
k_prep(const float* __restrict__ pr, const float* __restrict__ tg) {
    __shared__ int sh[NB];
    const int s = blockIdx.x;
    const int tid = threadIdx.x;
    const float* __restrict__ src = s ? tg : pr;

    sh[tid] = 0;
    __syncthreads();

    // histogram (16 points per thread)
#pragma unroll
    for (int k = 0; k < NPTS / PREPT; k++) {
        int i = tid + k * PREPT;
        atomicAdd(&sh[bin_of(src[3 * i])], 1);
    }
    __syncthreads();

    // inclusive Hillis-Steele scan over NB bins
    for (int d = 1; d < NB; d <<= 1) {
        int v = sh[tid];
        if (tid >= d) v += sh[tid - d];
        __syncthreads();
        sh[tid] = v;
        __syncthreads();
    }
    g_off[s][tid + 1] = sh[tid];
    if (tid == 0) g_off[s][0] = 0;

    // convert in-place to exclusive offsets (scatter cursors)
    {
        int excl = (tid > 0) ? sh[tid - 1] : 0;
        __syncthreads();
        sh[tid] = excl;
    }
    __syncthreads();

    // scatter + minbits init
#pragma unroll
    for (int k = 0; k < NPTS / PREPT; k++) {
        int i = tid + k * PREPT;
        float x = src[3 * i], y = src[3 * i + 1], z = src[3 * i + 2];
        int pos = atomicAdd(&sh[bin_of(x)], 1);
        g_pts[s][pos] = make_float4(x, y, z, 0.5f * (x * x + y * y + z * z));
        g_minbits[s][i] = 0xFFFFFFFFu;
    }
}

// ---------- K2: fixed-coverage search ----------
// blockIdx = (chunk c, seg s, pass). Ref chunk rc = c + s - 2.
__global__ void __launch_bounds__(TPB)
k_search() {
    const int c = blockIdx.x;
    const int rc = c + (int)blockIdx.y - 2;
    if (rc < 0 || rc >= NCHUNK) return;
    const int pass = blockIdx.z;
    const int qset = pass, rset = 1 - pass;
    const int tid = threadIdx.x;

    __shared__ float4 sref[CH];

    const float4* __restrict__ refs = g_pts[rset];
    {
        int b = rc * CH;
        sref[tid] = refs[b + tid];
        sref[tid + TPB] = refs[b + tid + TPB];
    }

    const int p0 = c * CH + tid;
    const int p1 = p0 + TPB;
    const float4 qa = g_pts[qset][p0];
    const float4 qb = g_pts[qset][p1];
    const float ax = -qa.x, ay = -qa.y, az = -qa.z;
    const float bx = -qb.x, by = -qb.y, bz = -qb.z;

    __syncthreads();

    const float INF = __int_as_float(0x7f800000);
    float ma0 = INF, ma1 = INF, mb0 = INF, mb1 = INF;

#pragma unroll 4
    for (int j = 0; j < CH; j += 2) {
        float4 t0 = sref[j];
        float4 t1 = sref[j + 1];
        float e;
        e = __fmaf_rn(ax, t0.x, t0.w); e = __fmaf_rn(ay, t0.y, e); e = __fmaf_rn(az, t0.z, e);
        ma0 = fminf(ma0, e);
        e = __fmaf_rn(bx, t0.x, t0.w); e = __fmaf_rn(by, t0.y, e); e = __fmaf_rn(bz, t0.z, e);
        mb0 = fminf(mb0, e);
        e = __fmaf_rn(ax, t1.x, t1.w); e = __fmaf_rn(ay, t1.y, e); e = __fmaf_rn(az, t1.z, e);
        ma1 = fminf(ma1, e);
        e = __fmaf_rn(bx, t1.x, t1.w); e = __fmaf_rn(by, t1.y, e); e = __fmaf_rn(bz, t1.z, e);
        mb1 = fminf(mb1, e);
    }

    atomicMin(&g_minbits[pass][p0], fflip(fminf(ma0, ma1)));
    atomicMin(&g_minbits[pass][p1], fflip(fminf(mb0, mb1)));
}

// ---------- K3: exact fixup + d2 materialization ----------
// One thread per (pass, binned query). Coverage was positions [pL, pR).
// Uncovered-left refs have x <= edge(bL+1); uncovered-right x >= edge(bR).
// Expand per-thread (rare) until the bin-edge lower bound dominates d2min.
__global__ void __launch_bounds__(FIXT)
k_fixup() {
    const int pass = blockIdx.y;
    const int qset = pass, rset = 1 - pass;
    const int p = blockIdx.x * FIXT + threadIdx.x;

    const float4 q = g_pts[qset][p];
    float m = funflip(g_minbits[pass][p]);

    const int c = p / CH;
    int pL = max((c - 2) * CH, 0);
    int pR = min((c + 3) * CH, NPTS);

    const float4* __restrict__ refs = g_pts[rset];
    const int* __restrict__ off = g_off[rset];

    // left expansion
    if (pL > 0) {
        int bL = bin_of(refs[pL].x);   // uncovered-left bins <= bL
        while (true) {
            float d2min = fmaxf(2.0f * (m + q.w), 0.0f);
            float lb = XMIN + (float)(bL + 1) * XW;   // upper bound on uncovered x
            float d = q.x - lb;
            if (d > 0.0f && d * d >= d2min) break;
            int nb = max(bL - (EXPB - 1), 0);
            for (int j = off[nb]; j < pL; j++) {
                float4 t = refs[j];
                float e = __fmaf_rn(-q.x, t.x, t.w);
                e = __fmaf_rn(-q.y, t.y, e);
                e = __fmaf_rn(-q.z, t.z, e);
                m = fminf(m, e);
            }
            pL = off[nb];
            if (pL == 0 || nb == 0) break;
            bL = nb - 1;
        }
    }
    // right expansion
    if (pR < NPTS) {
        int bR = bin_of(refs[pR - 1].x);   // uncovered-right bins >= bR
        while (true) {
            float d2min = fmaxf(2.0f * (m + q.w), 0.0f);
            float rb = XMIN + (float)bR * XW;          // lower bound on uncovered x
            float d = rb - q.x;
            if (d > 0.0f && d * d >= d2min) break;
            int nb = min(bR + (EXPB - 1), NB - 1);
            for (int j = pR; j < off[nb + 1]; j++) {
                float4 t = refs[j];
                float e = __fmaf_rn(-q.x, t.x, t.w);
                e = __fmaf_rn(-q.y, t.y, e);
                e = __fmaf_rn(-q.z, t.z, e);
                m = fminf(m, e);
            }
            pR = off[nb + 1];
            if (pR == NPTS || nb == NB - 1) break;
            bR = nb + 1;
        }
    }

    g_d2[pass][p] = fmaxf(2.0f * (m + q.w), 0.0f);
}

// ---------- K4: deterministic fixed-order reduction ----------
__global__ void __launch_bounds__(1024)
k_reduce(float* __restrict__ out) {
    __shared__ float sh[1024];
    const float* d2 = (const float*)g_d2;
    float s = 0.0f;
    for (int i = threadIdx.x; i < 2 * NPTS; i += 1024)
        s += d2[i];
    sh[threadIdx.x] = s;
    __syncthreads();
#pragma unroll
    for (int o = 512; o > 0; o >>= 1) {
        if (threadIdx.x < o) sh[threadIdx.x] += sh[threadIdx.x + o];
        __syncthreads();
    }
    if (threadIdx.x == 0)
        out[0] = sh[0] * (1.0f / (float)NPTS);
}

extern "C" void kernel_launch(void* const* d_in, const int* in_sizes, int n_in,
                              void* d_out, int out_size) {
    const float* pr = (const float*)d_in[0];   // predict [1,16384,3]
    const float* tg = (const float*)d_in[1];   // target  [1,16384,3]
    float* out = (float*)d_out;

    k_prep<<<2, PREPT>>>(pr, tg);

    dim3 sgrid(NCHUNK, KSEG, 2);
    k_search<<<sgrid, TPB>>>();

    dim3 fgrid(NPTS / FIXT, 2);
    k_fixup<<<fgrid, FIXT>>>();

    k_reduce<<<1, 1024>>>(out);
}

// round 7
// speedup vs baseline: 8.3435x; 6.7686x over previous
#include <cuda_runtime.h>

#define NPTS   16384
#define TPB    256
#define QPT    8                    // queries per thread (4 f32x2 pairs)
#define QCHUNK (TPB * QPT)          // 2048 queries per block
#define NCHUNK (NPTS / QCHUNK)      // 8
#define SEGS   32
#define SEGLEN (NPTS / SEGS)        // 512 refs per segment

typedef unsigned long long u64;
typedef unsigned int       u32;

// g_ref[p] = packed refs (x,y,z, 0.5*|t|^2) for pass p.
// p=0: refs = target (queries = predict). p=1: refs = predict.
__device__ float4 g_ref[2][NPTS];
__device__ u32    g_minbits[2][NPTS];

// ---- packed f32x2 helpers ----
__device__ __forceinline__ u64 pack2(float lo, float hi) {
    u64 r;
    asm("mov.b64 %0, {%1, %2};" : "=l"(r) : "f"(lo), "f"(hi));
    return r;
}
__device__ __forceinline__ u64 bcast2(float v) {
    u64 r;
    asm("mov.b64 %0, {%1, %1};" : "=l"(r) : "f"(v));
    return r;
}
__device__ __forceinline__ float2 unpack2(u64 v) {
    float2 r;
    asm("mov.b64 {%0, %1}, %2;" : "=f"(r.x), "=f"(r.y) : "l"(v));
    return r;
}
__device__ __forceinline__ u64 fma2(u64 a, u64 b, u64 c) {
    u64 d;
    asm("fma.rn.f32x2 %0, %1, %2, %3;" : "=l"(d) : "l"(a), "l"(b), "l"(c));
    return d;
}

// Order-preserving float <-> uint flip (min over floats == min over flipped uints)
__device__ __forceinline__ u32 fflip(float f) {
    u32 u = __float_as_uint(f);
    return (u & 0x80000000u) ? ~u : (u | 0x80000000u);
}
__device__ __forceinline__ float funflip(u32 u) {
    u = (u & 0x80000000u) ? (u ^ 0x80000000u) : ~u;
    return __uint_as_float(u);
}

__global__ void chamfer_prep(const float* __restrict__ pr,
                             const float* __restrict__ tg) {
    int i = blockIdx.x * blockDim.x + threadIdx.x;
    if (i >= NPTS) return;
    float x = tg[3 * i], y = tg[3 * i + 1], z = tg[3 * i + 2];
    g_ref[0][i] = make_float4(x, y, z, 0.5f * (x * x + y * y + z * z));
    x = pr[3 * i]; y = pr[3 * i + 1]; z = pr[3 * i + 2];
    g_ref[1][i] = make_float4(x, y, z, 0.5f * (x * x + y * y + z * z));
    g_minbits[0][i] = 0xFFFFFFFFu;
    g_minbits[1][i] = 0xFFFFFFFFu;
}

// One block: QCHUNK queries x one SEGLEN-ref segment.
// Two queries packed per f32x2 register (loop-invariant); each ref broadcast
// into both halves (4 MOVs/iter). e = 0.5|t|^2 - q.t, 2 queries per FFMA2.
__global__ void __launch_bounds__(TPB)
chamfer_pass(const float* __restrict__ pr, const float* __restrict__ tg) {
    const int pass = blockIdx.z;
    const float* __restrict__ qsrc = (pass == 0) ? pr : tg;
    const float4* __restrict__ ref = g_ref[pass];

    __shared__ float4 sref[SEGLEN];

    const int segBase = blockIdx.y * SEGLEN;
    {
        int t = threadIdx.x;                 // SEGLEN == 2*TPB
        sref[t] = ref[segBase + t];
        sref[t + TPB] = ref[segBase + t + TPB];
    }

    const int qb = blockIdx.x * QCHUNK + threadIdx.x;
    u64 NX[QPT / 2], NY[QPT / 2], NZ[QPT / 2];
#pragma unroll
    for (int m = 0; m < QPT / 2; m++) {
        int qa = qb + (2 * m) * TPB;
        int qc = qb + (2 * m + 1) * TPB;
        NX[m] = pack2(-qsrc[3 * qa],     -qsrc[3 * qc]);
        NY[m] = pack2(-qsrc[3 * qa + 1], -qsrc[3 * qc + 1]);
        NZ[m] = pack2(-qsrc[3 * qa + 2], -qsrc[3 * qc + 2]);
    }

    __syncthreads();

    const float INF = __int_as_float(0x7f800000);
    float mn[QPT];
#pragma unroll
    for (int k = 0; k < QPT; k++) mn[k] = INF;

#pragma unroll 2
    for (int j = 0; j < SEGLEN; j++) {
        const float4 t = sref[j];            // LDS.128 broadcast
        const u64 X = bcast2(t.x);
        const u64 Y = bcast2(t.y);
        const u64 Z = bcast2(t.z);
        const u64 W = bcast2(t.w);
#pragma unroll
        for (int m = 0; m < QPT / 2; m++) {
            u64 e = fma2(NX[m], X, W);
            e = fma2(NY[m], Y, e);
            e = fma2(NZ[m], Z, e);
            float2 ef = unpack2(e);
            mn[2 * m]     = fminf(mn[2 * m],     ef.x);
            mn[2 * m + 1] = fminf(mn[2 * m + 1], ef.y);
        }
    }

#pragma unroll
    for (int k = 0; k < QPT; k++)
        atomicMin(&g_minbits[pass][qb + k * TPB], fflip(mn[k]));
}

// d_q = max(2*min_e + |q|^2, 0);  loss = (sum_pass0 + sum_pass1) / NPTS
__global__ void __launch_bounds__(1024)
chamfer_reduce(const float* __restrict__ pr, const float* __restrict__ tg,
               float* __restrict__ out) {
    __shared__ float sh[1024];
    float s = 0.0f;
    for (int i = threadIdx.x; i < NPTS; i += 1024) {
        float x = pr[3 * i], y = pr[3 * i + 1], z = pr[3 * i + 2];
        float q2 = x * x + y * y + z * z;
        float d = __fmaf_rn(2.0f, funflip(g_minbits[0][i]), q2);
        s += fmaxf(d, 0.0f);

        x = tg[3 * i]; y = tg[3 * i + 1]; z = tg[3 * i + 2];
        q2 = x * x + y * y + z * z;
        d = __fmaf_rn(2.0f, funflip(g_minbits[1][i]), q2);
        s += fmaxf(d, 0.0f);
    }
    sh[threadIdx.x] = s;
    __syncthreads();
#pragma unroll
    for (int off = 512; off > 0; off >>= 1) {
        if (threadIdx.x < off) sh[threadIdx.x] += sh[threadIdx.x + off];
        __syncthreads();
    }
    if (threadIdx.x == 0)
        out[0] = sh[0] * (1.0f / (float)NPTS);
}

extern "C" void kernel_launch(void* const* d_in, const int* in_sizes, int n_in,
                              void* d_out, int out_size) {
    const float* pr = (const float*)d_in[0];   // predict [1,16384,3]
    const float* tg = (const float*)d_in[1];   // target  [1,16384,3]
    float* out = (float*)d_out;

    chamfer_prep<<<(NPTS + TPB - 1) / TPB, TPB>>>(pr, tg);

    dim3 grid(NCHUNK, SEGS, 2);
    chamfer_pass<<<grid, TPB>>>(pr, tg);

    chamfer_reduce<<<1, 1024>>>(pr, tg, out);
}

// round 8
// speedup vs baseline: 8.8159x; 1.0566x over previous
#include <cuda_runtime.h>

#define NPTS   16384
#define NB     1024
#define XMIN   (-5.0f)
#define XW     (10.0f / (float)NB)
#define INVW   ((float)NB / 10.0f)
#define CH     512                        // queries per chunk / refs per segment
#define NCHUNK (NPTS / CH)                // 32
#define TPB    256
#define PREPT  1024

typedef unsigned int u32;

// set 0 = predict, set 1 = target; pass p: queries = set p, refs = set 1-p
__device__ float4 g_pts[2][NPTS];         // x-binned points (x,y,z, 0.5*|p|^2)
__device__ u32    g_minbits[2][NPTS];     // flipped min-e per binned query
__device__ float  g_cmax[2][NCHUNK];      // per-chunk max d2 upper bound
__device__ float  g_xmin[2][NCHUNK];      // exact chunk x extents
__device__ float  g_xmax[2][NCHUNK];

__device__ __forceinline__ int bin_of(float x) {
    int b = (int)((x - XMIN) * INVW);
    return min(max(b, 0), NB - 1);
}
__device__ __forceinline__ u32 fflip(float f) {
    u32 u = __float_as_uint(f);
    return (u & 0x80000000u) ? ~u : (u | 0x80000000u);
}
__device__ __forceinline__ float funflip(u32 u) {
    u = (u & 0x80000000u) ? (u ^ 0x80000000u) : ~u;
    return __uint_as_float(u);
}

// ---------- K1: fused prep (one block per set) — validated in R6 ----------
__global__ void __launch_bounds__(PREPT)
k_prep(const float* __restrict__ pr, const float* __restrict__ tg) {
    __shared__ int sh[NB];
    const int s = blockIdx.x;
    const int tid = threadIdx.x;
    const float* __restrict__ src = s ? tg : pr;

    sh[tid] = 0;
    __syncthreads();

#pragma unroll
    for (int k = 0; k < NPTS / PREPT; k++) {
        int i = tid + k * PREPT;
        atomicAdd(&sh[bin_of(src[3 * i])], 1);
    }
    __syncthreads();

    // inclusive scan
    for (int d = 1; d < NB; d <<= 1) {
        int v = sh[tid];
        if (tid >= d) v += sh[tid - d];
        __syncthreads();
        sh[tid] = v;
        __syncthreads();
    }
    // to exclusive (scatter cursors)
    {
        int excl = (tid > 0) ? sh[tid - 1] : 0;
        __syncthreads();
        sh[tid] = excl;
    }
    __syncthreads();

#pragma unroll
    for (int k = 0; k < NPTS / PREPT; k++) {
        int i = tid + k * PREPT;
        float x = src[3 * i], y = src[3 * i + 1], z = src[3 * i + 2];
        int pos = atomicAdd(&sh[bin_of(x)], 1);
        g_pts[s][pos] = make_float4(x, y, z, 0.5f * (x * x + y * y + z * z));
        g_minbits[s][i] = 0xFFFFFFFFu;
    }
}

// ---------- dense chunk-vs-segment evaluation (identical in all callers) ----------
__device__ __forceinline__ void eval_block(int c, int s, int pass, float4* sref) {
    const int tid = threadIdx.x;
    const float4* __restrict__ refs = g_pts[1 - pass];
    {
        int b = s * CH;
        sref[tid] = refs[b + tid];
        sref[tid + TPB] = refs[b + tid + TPB];
    }

    const int p0 = c * CH + tid;
    const int p1 = p0 + TPB;
    const float4 qa = g_pts[pass][p0];
    const float4 qb = g_pts[pass][p1];
    const float ax = -qa.x, ay = -qa.y, az = -qa.z;
    const float bx = -qb.x, by = -qb.y, bz = -qb.z;

    __syncthreads();

    const float INF = __int_as_float(0x7f800000);
    float ma0 = INF, ma1 = INF, mb0 = INF, mb1 = INF;

#pragma unroll 4
    for (int j = 0; j < CH; j += 2) {
        float4 t0 = sref[j];
        float4 t1 = sref[j + 1];
        float e;
        e = __fmaf_rn(ax, t0.x, t0.w); e = __fmaf_rn(ay, t0.y, e); e = __fmaf_rn(az, t0.z, e);
        ma0 = fminf(ma0, e);
        e = __fmaf_rn(bx, t0.x, t0.w); e = __fmaf_rn(by, t0.y, e); e = __fmaf_rn(bz, t0.z, e);
        mb0 = fminf(mb0, e);
        e = __fmaf_rn(ax, t1.x, t1.w); e = __fmaf_rn(ay, t1.y, e); e = __fmaf_rn(az, t1.z, e);
        ma1 = fminf(ma1, e);
        e = __fmaf_rn(bx, t1.x, t1.w); e = __fmaf_rn(by, t1.y, e); e = __fmaf_rn(bz, t1.z, e);
        mb1 = fminf(mb1, e);
    }

    atomicMin(&g_minbits[pass][p0], fflip(fminf(ma0, ma1)));
    atomicMin(&g_minbits[pass][p1], fflip(fminf(mb0, mb1)));
}

// ---------- K2: diagonal band (refs chunks c-1..c+1) ----------
__global__ void __launch_bounds__(TPB)
k_diag() {
    const int c = blockIdx.x;
    const int s = c + (int)blockIdx.y - 1;
    if (s < 0 || s >= NCHUNK) return;
    __shared__ float4 sref[CH];
    eval_block(c, s, blockIdx.z, sref);
}

// ---------- K3: per-chunk bounds (max d2, exact x extents) ----------
__global__ void __launch_bounds__(TPB)
k_bounds() {
    __shared__ float sd[TPB], sl[TPB], sr[TPB];
    const int c = blockIdx.x, p = blockIdx.y, tid = threadIdx.x;
    const float INF = __int_as_float(0x7f800000);
    float dmax = 0.0f, xmn = INF, xmx = -INF;
#pragma unroll
    for (int k = 0; k < CH / TPB; k++) {
        int i = c * CH + tid + k * TPB;
        float4 q = g_pts[p][i];
        float m = funflip(g_minbits[p][i]);
        float d2 = fmaxf(2.0f * (m + q.w), 0.0f);
        dmax = fmaxf(dmax, d2);
        xmn = fminf(xmn, q.x);
        xmx = fmaxf(xmx, q.x);
    }
    sd[tid] = dmax; sl[tid] = xmn; sr[tid] = xmx;
    __syncthreads();
#pragma unroll
    for (int o = TPB / 2; o > 0; o >>= 1) {
        if (tid < o) {
            sd[tid] = fmaxf(sd[tid], sd[tid + o]);
            sl[tid] = fminf(sl[tid], sl[tid + o]);
            sr[tid] = fmaxf(sr[tid], sr[tid + o]);
        }
        __syncthreads();
    }
    if (tid == 0) {
        g_cmax[p][c] = sd[0];
        g_xmin[p][c] = sl[0];
        g_xmax[p][c] = sr[0];
    }
}

// ---------- K4: off-diagonal with sound block-level skip ----------
__global__ void __launch_bounds__(TPB)
k_off() {
    const int c = blockIdx.x, s = blockIdx.y, p = blockIdx.z;
    const int d = s - c;
    if (d >= -1 && d <= 1) return;                 // covered by k_diag

    // exact 1-D lower bound on any query-ref distance between chunk c and seg s
    float gap = (s > c) ? (g_xmin[1 - p][s] - g_xmax[p][c])
                        : (g_xmin[p][c] - g_xmax[1 - p][s]);
    if (gap > 0.0f && gap * gap >= g_cmax[p][c]) return;   // cannot improve any query

    __shared__ float4 sref[CH];
    eval_block(c, s, p, sref);
}

// ---------- K5: deterministic reduction ----------
__global__ void __launch_bounds__(1024)
k_reduce(float* __restrict__ out) {
    __shared__ float sh[1024];
    float sum = 0.0f;
#pragma unroll
    for (int p = 0; p < 2; p++) {
        for (int i = threadIdx.x; i < NPTS; i += 1024) {
            float4 q = g_pts[p][i];
            float m = funflip(g_minbits[p][i]);
            sum += fmaxf(2.0f * (m + q.w), 0.0f);
        }
    }
    sh[threadIdx.x] = sum;
    __syncthreads();
#pragma unroll
    for (int o = 512; o > 0; o >>= 1) {
        if (threadIdx.x < o) sh[threadIdx.x] += sh[threadIdx.x + o];
        __syncthreads();
    }
    if (threadIdx.x == 0)
        out[0] = sh[0] * (1.0f / (float)NPTS);
}

extern "C" void kernel_launch(void* const* d_in, const int* in_sizes, int n_in,
                              void* d_out, int out_size) {
    const float* pr = (const float*)d_in[0];   // predict [1,16384,3]
    const float* tg = (const float*)d_in[1];   // target  [1,16384,3]
    float* out = (float*)d_out;

    k_prep<<<2, PREPT>>>(pr, tg);

    dim3 dgrid(NCHUNK, 3, 2);
    k_diag<<<dgrid, TPB>>>();

    dim3 bgrid(NCHUNK, 2);
    k_bounds<<<bgrid, TPB>>>();

    dim3 ogrid(NCHUNK, NCHUNK, 2);
    k_off<<<ogrid, TPB>>>();

    k_reduce<<<1, 1024>>>(out);
}

// round 9
// speedup vs baseline: 12.1446x; 1.3776x over previous
#include <cuda_runtime.h>

#define NPTS   16384
#define NB     1024
#define YB     64
#define XMIN   (-5.0f)
#define INVW   ((float)NB / 10.0f)
#define SLAB   512
#define NSLAB  (NPTS / SLAB)              // 32
#define CELL   128
#define NCELL  (NPTS / CELL)              // 128
#define TPB    256
#define PREPT  1024

typedef unsigned int u32;

// set 0 = predict, set 1 = target; pass p: queries = set p, refs = set 1-p
__device__ float4 g_pts[2][NPTS];         // x-slab then y-sorted (x,y,z, 0.5|p|^2)
__device__ u32    g_minbits[2][NPTS];
__device__ float4 g_ext[2][NCELL];        // per-cell (xmin, xmax, ymin, ymax)
__device__ float  g_cmax[2][NCELL];       // per query-cell max d2 after diag

__device__ __forceinline__ int bin_of(float x) {
    int b = (int)((x - XMIN) * INVW);
    return min(max(b, 0), NB - 1);
}
__device__ __forceinline__ u32 fflip(float f) {
    u32 u = __float_as_uint(f);
    return (u & 0x80000000u) ? ~u : (u | 0x80000000u);
}
__device__ __forceinline__ float funflip(u32 u) {
    u = (u & 0x80000000u) ? (u ^ 0x80000000u) : ~u;
    return __uint_as_float(u);
}

// ---------- K1: fused x-bin sort (validated R6/R8) ----------
__global__ void __launch_bounds__(PREPT)
k_prep(const float* __restrict__ pr, const float* __restrict__ tg) {
    __shared__ int sh[NB];
    const int s = blockIdx.x;
    const int tid = threadIdx.x;
    const float* __restrict__ src = s ? tg : pr;

    sh[tid] = 0;
    __syncthreads();
#pragma unroll
    for (int k = 0; k < NPTS / PREPT; k++) {
        int i = tid + k * PREPT;
        atomicAdd(&sh[bin_of(src[3 * i])], 1);
    }
    __syncthreads();
    for (int d = 1; d < NB; d <<= 1) {
        int v = sh[tid];
        if (tid >= d) v += sh[tid - d];
        __syncthreads();
        sh[tid] = v;
        __syncthreads();
    }
    {
        int excl = (tid > 0) ? sh[tid - 1] : 0;
        __syncthreads();
        sh[tid] = excl;
    }
    __syncthreads();
#pragma unroll
    for (int k = 0; k < NPTS / PREPT; k++) {
        int i = tid + k * PREPT;
        float x = src[3 * i], y = src[3 * i + 1], z = src[3 * i + 2];
        int pos = atomicAdd(&sh[bin_of(x)], 1);
        g_pts[s][pos] = make_float4(x, y, z, 0.5f * (x * x + y * y + z * z));
        g_minbits[s][i] = 0xFFFFFFFFu;
    }
}

// ---------- K2: y-sort each 512-pt slab (bin-scatter into 64 y-bins) ----------
__global__ void __launch_bounds__(SLAB)
k_ysort() {
    __shared__ float4 buf[SLAB];
    __shared__ int hist[YB];
    __shared__ int cur[YB];
    const int slab = blockIdx.x, set = blockIdx.y, tid = threadIdx.x;
    const int base = slab * SLAB;

    float4 pt = g_pts[set][base + tid];
    if (tid < YB) hist[tid] = 0;
    __syncthreads();
    int yb = min(max((int)((pt.y - XMIN) * ((float)YB / 10.0f)), 0), YB - 1);
    atomicAdd(&hist[yb], 1);
    __syncthreads();
    if (tid == 0) {
        int acc = 0;
        for (int b = 0; b < YB; b++) { int v = hist[b]; cur[b] = acc; acc += v; }
    }
    __syncthreads();
    int pos = atomicAdd(&cur[yb], 1);
    buf[pos] = pt;
    __syncthreads();
    g_pts[set][base + tid] = buf[tid];
}

// ---------- K3: diagonal band — query cell vs 3 ref slabs ----------
__global__ void __launch_bounds__(CELL)
k_diag() {
    const int qc = blockIdx.x;
    const int sd = (int)blockIdx.y - 1;
    const int pass = blockIdx.z;
    const int rslab = (qc >> 2) + sd;
    if (rslab < 0 || rslab >= NSLAB) return;
    const int tid = threadIdx.x;

    __shared__ float4 sref[SLAB];
    const float4* __restrict__ refs = g_pts[1 - pass];
    {
        int rb = rslab * SLAB;
#pragma unroll
        for (int k = 0; k < SLAB / CELL; k++)
            sref[tid + k * CELL] = refs[rb + tid + k * CELL];
    }

    const int qp = qc * CELL + tid;
    const float4 q = g_pts[pass][qp];
    const float nx = -q.x, ny = -q.y, nz = -q.z;
    __syncthreads();

    const float INF = __int_as_float(0x7f800000);
    float m0 = INF, m1 = INF;
#pragma unroll 4
    for (int j = 0; j < SLAB; j += 2) {
        float4 t0 = sref[j];
        float4 t1 = sref[j + 1];
        float e;
        e = __fmaf_rn(nx, t0.x, t0.w); e = __fmaf_rn(ny, t0.y, e); e = __fmaf_rn(nz, t0.z, e);
        m0 = fminf(m0, e);
        e = __fmaf_rn(nx, t1.x, t1.w); e = __fmaf_rn(ny, t1.y, e); e = __fmaf_rn(nz, t1.z, e);
        m1 = fminf(m1, e);
    }
    atomicMin(&g_minbits[pass][qp], fflip(fminf(m0, m1)));
}

// ---------- K4: per-cell exact extents + cmax ----------
__global__ void __launch_bounds__(CELL)
k_bounds() {
    __shared__ float sxn[CELL], sxm[CELL], syn[CELL], sym[CELL], sd2[CELL];
    const int cell = blockIdx.x, set = blockIdx.y, tid = threadIdx.x;
    const int i = cell * CELL + tid;
    float4 q = g_pts[set][i];
    float m = funflip(g_minbits[set][i]);
    float d2 = fmaxf(2.0f * (m + q.w), 0.0f);
    sxn[tid] = q.x; sxm[tid] = q.x;
    syn[tid] = q.y; sym[tid] = q.y;
    sd2[tid] = d2;
    __syncthreads();
#pragma unroll
    for (int o = CELL / 2; o > 0; o >>= 1) {
        if (tid < o) {
            sxn[tid] = fminf(sxn[tid], sxn[tid + o]);
            sxm[tid] = fmaxf(sxm[tid], sxm[tid + o]);
            syn[tid] = fminf(syn[tid], syn[tid + o]);
            sym[tid] = fmaxf(sym[tid], sym[tid + o]);
            sd2[tid] = fmaxf(sd2[tid], sd2[tid + o]);
        }
        __syncthreads();
    }
    if (tid == 0) {
        g_ext[set][cell] = make_float4(sxn[0], sxm[0], syn[0], sym[0]);
        g_cmax[set][cell] = sd2[0];
    }
}

// ---------- K5: off-diagonal cells with sound 2-D skip ----------
__global__ void __launch_bounds__(64)
k_off() {
    const int qc = blockIdx.x, rc = blockIdx.y, p = blockIdx.z;
    const int sd = (rc >> 2) - (qc >> 2);
    if (sd >= -1 && sd <= 1) return;              // covered by k_diag

    const float4 eq = g_ext[p][qc];               // (xmin,xmax,ymin,ymax)
    const float4 er = g_ext[1 - p][rc];
    float gx = fmaxf(fmaxf(er.x - eq.y, eq.x - er.y), 0.0f);
    float gy = fmaxf(fmaxf(er.z - eq.w, eq.z - er.w), 0.0f);
    if (gx * gx + gy * gy >= g_cmax[p][qc]) return;   // cannot improve any query

    const int tid = threadIdx.x;
    __shared__ float4 sref[CELL];
    const float4* __restrict__ refs = g_pts[1 - p];
    {
        int rb = rc * CELL;
        sref[tid] = refs[rb + tid];
        sref[tid + 64] = refs[rb + tid + 64];
    }
    const int p0 = qc * CELL + tid;
    const int p1 = p0 + 64;
    const float4 qa = g_pts[p][p0];
    const float4 qb = g_pts[p][p1];
    const float ax = -qa.x, ay = -qa.y, az = -qa.z;
    const float bx = -qb.x, by = -qb.y, bz = -qb.z;
    __syncthreads();

    const float INF = __int_as_float(0x7f800000);
    float ma0 = INF, ma1 = INF, mb0 = INF, mb1 = INF;
#pragma unroll 4
    for (int j = 0; j < CELL; j += 2) {
        float4 t0 = sref[j];
        float4 t1 = sref[j + 1];
        float e;
        e = __fmaf_rn(ax, t0.x, t0.w); e = __fmaf_rn(ay, t0.y, e); e = __fmaf_rn(az, t0.z, e);
        ma0 = fminf(ma0, e);
        e = __fmaf_rn(bx, t0.x, t0.w); e = __fmaf_rn(by, t0.y, e); e = __fmaf_rn(bz, t0.z, e);
        mb0 = fminf(mb0, e);
        e = __fmaf_rn(ax, t1.x, t1.w); e = __fmaf_rn(ay, t1.y, e); e = __fmaf_rn(az, t1.z, e);
        ma1 = fminf(ma1, e);
        e = __fmaf_rn(bx, t1.x, t1.w); e = __fmaf_rn(by, t1.y, e); e = __fmaf_rn(bz, t1.z, e);
        mb1 = fminf(mb1, e);
    }
    atomicMin(&g_minbits[p][p0], fflip(fminf(ma0, ma1)));
    atomicMin(&g_minbits[p][p1], fflip(fminf(mb0, mb1)));
}

// ---------- K6: deterministic reduction ----------
__global__ void __launch_bounds__(1024)
k_reduce(float* __restrict__ out) {
    __shared__ float sh[1024];
    float sum = 0.0f;
#pragma unroll
    for (int p = 0; p < 2; p++) {
        for (int i = threadIdx.x; i < NPTS; i += 1024) {
            float4 q = g_pts[p][i];
            float m = funflip(g_minbits[p][i]);
            sum += fmaxf(2.0f * (m + q.w), 0.0f);
        }
    }
    sh[threadIdx.x] = sum;
    __syncthreads();
#pragma unroll
    for (int o = 512; o > 0; o >>= 1) {
        if (threadIdx.x < o) sh[threadIdx.x] += sh[threadIdx.x + o];
        __syncthreads();
    }
    if (threadIdx.x == 0)
        out[0] = sh[0] * (1.0f / (float)NPTS);
}

extern "C" void kernel_launch(void* const* d_in, const int* in_sizes, int n_in,
                              void* d_out, int out_size) {
    const float* pr = (const float*)d_in[0];   // predict [1,16384,3]
    const float* tg = (const float*)d_in[1];   // target  [1,16384,3]
    float* out = (float*)d_out;

    k_prep<<<2, PREPT>>>(pr, tg);

    dim3 ygrid(NSLAB, 2);
    k_ysort<<<ygrid, SLAB>>>();

    dim3 dgrid(NCELL, 3, 2);
    k_diag<<<dgrid, CELL>>>();

    dim3 bgrid(NCELL, 2);
    k_bounds<<<bgrid, CELL>>>();

    dim3 ogrid(NCELL, NCELL, 2);
    k_off<<<ogrid, 64>>>();

    k_reduce<<<1, 1024>>>(out);
}